// round 8
// baseline (speedup 1.0000x reference)
#include <cuda_runtime.h>
#include <cuda_fp16.h>
#include <math.h>

#define N_NODES 100000
#define DIN     512
#define NE      1600000
#define ET      (NE + N_NODES)   // edges + self loops
#define NEG_SLOPE 0.2f
#define NPART   ((N_NODES + 1023) / 1024)
#define WT_K    520              // padded k stride

// ---------------- scratch (device globals) -------------------------------------
__device__ __align__(128) __half g_Wt[64 * WT_K];              // W^T as half [n][k]
__device__ __align__(128) __half g_Hh[(size_t)N_NODES * 64];   // fp16 messages L1
__device__ __align__(128) float  g_als[N_NODES * 8];
__device__ __align__(128) float  g_ald[N_NODES * 8];
__device__ __align__(128) __half g_h3h[(size_t)N_NODES * 16];  // fp16 messages L2
__device__ __align__(128) float  g_al2s[N_NODES];
__device__ __align__(128) float  g_al2d[N_NODES];
__device__ int g_src[ET];
__device__ int g_dst[ET];
__device__ int g_esrc[ET];
__device__ int g_deg[N_NODES];
__device__ int g_off[N_NODES + 1];
__device__ int g_cur[N_NODES];
__device__ int g_part[NPART];
__device__ int g_is64;

__device__ __forceinline__ float2 h2f2(unsigned u) {
    __half2 h = *reinterpret_cast<const __half2*>(&u);
    return __half22float2(h);
}

// ---------------- edge-index dtype detection (JAX x64-off downcast) ------------
__global__ void k_detect(const int* __restrict__ ei32) {
    int allzero = 1;
    for (int i = 0; i < 128; i++)
        if (ei32[2 * i + 1] != 0) { allzero = 0; break; }
    g_is64 = allzero;
}

// prep + degree count fused
__global__ void k_prep_edges(const void* __restrict__ ei) {
    int e = blockIdx.x * blockDim.x + threadIdx.x;
    if (e >= ET) return;
    int s, d;
    if (e < NE) {
        if (g_is64) {
            const long long* p = (const long long*)ei;
            s = (int)p[e];
            d = (int)p[(size_t)NE + e];
        } else {
            const int* p = (const int*)ei;
            s = p[e];
            d = p[NE + e];
        }
        s = min(max(s, 0), N_NODES - 1);
        d = min(max(d, 0), N_NODES - 1);
    } else {
        s = e - NE;
        d = e - NE;
    }
    g_src[e] = s;
    g_dst[e] = d;
    atomicAdd(&g_deg[d], 1);
}

// g_Wt[n][k] = (half) W_hidden[n/8][k][n%8]
__global__ void k_prep_w(const float* __restrict__ Wh) {
    int i = blockIdx.x * blockDim.x + threadIdx.x;
    if (i >= 64 * DIN) return;
    int n = i >> 9, k = i & 511;
    int l = n >> 3, f = n & 7;
    g_Wt[n * WT_K + k] = __float2half(Wh[(size_t)l * (DIN * 8) + k * 8 + f]);
}

// ---------------- CSR build: scan + scatter --------------------------------------
__global__ __launch_bounds__(1024) void k_scan1() {
    __shared__ int wsum[32];
    int t = threadIdx.x, b = blockIdx.x;
    int i = b * 1024 + t;
    int v = (i < N_NODES) ? g_deg[i] : 0;
    int x = v;
    int lane = t & 31, w = t >> 5;
#pragma unroll
    for (int o = 1; o < 32; o <<= 1) {
        int y = __shfl_up_sync(0xffffffffu, x, o);
        if (lane >= o) x += y;
    }
    if (lane == 31) wsum[w] = x;
    __syncthreads();
    if (t < 32) {
        int y = wsum[t];
#pragma unroll
        for (int o = 1; o < 32; o <<= 1) {
            int z = __shfl_up_sync(0xffffffffu, y, o);
            if (t >= o) y += z;
        }
        wsum[t] = y;
    }
    __syncthreads();
    int excl = x - v + (w > 0 ? wsum[w - 1] : 0);
    if (i < N_NODES) g_off[i] = excl;
    if (t == 0) g_part[b] = wsum[31];
}

__global__ void k_scan2() {
    int t = threadIdx.x;
    int base = 0;
    for (int s = 0; s < NPART; s += 32) {
        int i = s + t;
        int v = (i < NPART) ? g_part[i] : 0;
        int x = v;
#pragma unroll
        for (int o = 1; o < 32; o <<= 1) {
            int y = __shfl_up_sync(0xffffffffu, x, o);
            if (t >= o) x += y;
        }
        if (i < NPART) g_part[i] = base + x - v;
        base += __shfl_sync(0xffffffffu, x, 31);
    }
}

__global__ void k_scan3() {
    int i = blockIdx.x * blockDim.x + threadIdx.x;
    if (i >= N_NODES) return;
    int o = g_off[i] + g_part[i >> 10];
    g_off[i] = o;
    g_cur[i] = o;
    if (i == 0) g_off[N_NODES] = ET;
}

__global__ void k_scatter() {
    int e = blockIdx.x * blockDim.x + threadIdx.x;
    if (e >= ET) return;
    int d = g_dst[e];
    int pos = atomicAdd(&g_cur[d], 1);
    g_esrc[pos] = g_src[e];
}

// ---------------- tensor-core GEMM: H = x @ W (fp16 HMMA, fp32 acc) -------------
#define GROWS 128
#define AKC   64
#define APAD  72
__global__ __launch_bounds__(256) void k_gemm(const float* __restrict__ x,
                                              const float* __restrict__ asrc,
                                              const float* __restrict__ adst) {
    extern __shared__ char smem[];
    __half* As = (__half*)smem;                       // [128][72]
    __half* Ws = (__half*)(smem + GROWS * APAD * 2);  // [64][520]

    const int t = threadIdx.x;
    const int w = t >> 5;
    const int l = t & 31;
    const int row0 = blockIdx.x * GROWS;
    const int g = l >> 2;
    const int q = l & 3;

    {
        const uint4* src = (const uint4*)g_Wt;
#pragma unroll
        for (int i = 0; i < 16; i++) {
            int idx = i * 256 + t;
            int r = idx >> 6, c = idx & 63;
            *(uint4*)&Ws[r * WT_K + c * 8] = src[(r * WT_K + c * 8) >> 3];
        }
    }

    float acc[8][4];
#pragma unroll
    for (int n = 0; n < 8; n++)
#pragma unroll
        for (int j = 0; j < 4; j++) acc[n][j] = 0.f;

    const int arow = (l & 7) + ((l & 8) ? 8 : 0);
    const int acol = (l & 16) ? 8 : 0;

    __syncthreads();

    for (int kt = 0; kt < DIN; kt += AKC) {
#pragma unroll
        for (int i = 0; i < 8; i++) {
            int idx = i * 256 + t;
            int r = idx >> 4, c4 = idx & 15;
            int rg = row0 + r; if (rg >= N_NODES) rg = N_NODES - 1;
            float4 v = *(const float4*)&x[(size_t)rg * DIN + kt + c4 * 4];
            __half2* dst = (__half2*)&As[r * APAD + c4 * 4];
            dst[0] = __floats2half2_rn(v.x, v.y);
            dst[1] = __floats2half2_rn(v.z, v.w);
        }
        __syncthreads();

#pragma unroll
        for (int k0 = 0; k0 < AKC; k0 += 16) {
            unsigned a0, a1, a2, a3;
            unsigned aaddr = __cvta_generic_to_shared(
                &As[(w * 16 + arow) * APAD + k0 + acol]);
            asm volatile("ldmatrix.sync.aligned.m8n8.x4.shared.b16 {%0,%1,%2,%3}, [%4];"
                         : "=r"(a0), "=r"(a1), "=r"(a2), "=r"(a3) : "r"(aaddr));
            int kg = kt + k0;
#pragma unroll
            for (int nt = 0; nt < 8; nt++) {
                int n = nt * 8 + g;
                unsigned b0 = *(const unsigned*)&Ws[n * WT_K + kg + 2 * q];
                unsigned b1 = *(const unsigned*)&Ws[n * WT_K + kg + 8 + 2 * q];
                asm volatile(
                    "mma.sync.aligned.m16n8k16.row.col.f32.f16.f16.f32 "
                    "{%0,%1,%2,%3}, {%4,%5,%6,%7}, {%8,%9}, {%0,%1,%2,%3};"
                    : "+f"(acc[nt][0]), "+f"(acc[nt][1]), "+f"(acc[nt][2]), "+f"(acc[nt][3])
                    : "r"(a0), "r"(a1), "r"(a2), "r"(a3), "r"(b0), "r"(b1));
            }
        }
        __syncthreads();
    }

    int row_lo = row0 + w * 16 + g;
    int row_hi = row_lo + 8;
#pragma unroll
    for (int nt = 0; nt < 8; nt++) {
        int c0 = nt * 8 + 2 * q, c1 = c0 + 1;
        if (row_lo < N_NODES)
            *(__half2*)&g_Hh[(size_t)row_lo * 64 + c0] = __floats2half2_rn(acc[nt][0], acc[nt][1]);
        if (row_hi < N_NODES)
            *(__half2*)&g_Hh[(size_t)row_hi * 64 + c0] = __floats2half2_rn(acc[nt][2], acc[nt][3]);
        float as0 = asrc[c0], as1 = asrc[c1], ad0 = adst[c0], ad1 = adst[c1];
        float psl_s = acc[nt][0] * as0 + acc[nt][1] * as1;
        float psl_d = acc[nt][0] * ad0 + acc[nt][1] * ad1;
        float psh_s = acc[nt][2] * as0 + acc[nt][3] * as1;
        float psh_d = acc[nt][2] * ad0 + acc[nt][3] * ad1;
        psl_s += __shfl_xor_sync(0xffffffffu, psl_s, 1);
        psl_s += __shfl_xor_sync(0xffffffffu, psl_s, 2);
        psl_d += __shfl_xor_sync(0xffffffffu, psl_d, 1);
        psl_d += __shfl_xor_sync(0xffffffffu, psl_d, 2);
        psh_s += __shfl_xor_sync(0xffffffffu, psh_s, 1);
        psh_s += __shfl_xor_sync(0xffffffffu, psh_s, 2);
        psh_d += __shfl_xor_sync(0xffffffffu, psh_d, 1);
        psh_d += __shfl_xor_sync(0xffffffffu, psh_d, 2);
        if (q == 0) {
            if (row_lo < N_NODES) { g_als[row_lo * 8 + nt] = psl_s; g_ald[row_lo * 8 + nt] = psl_d; }
            if (row_hi < N_NODES) { g_als[row_hi * 8 + nt] = psh_s; g_ald[row_hi * 8 + nt] = psh_d; }
        }
    }
}

// ---------------- layer 1: warp per node, 4 edges x 8 lanes ---------------------
// lane = eg*8 + lj: edge-group eg (0..3) handles every 4th edge; lane's layer lj.
// Per 4-edge iteration the warp issues ~9 L1tex wavefronts (vs ~40 thread-per-node).
__global__ __launch_bounds__(256) void k_edge1w(const float* __restrict__ bias_h,
                                                const float* __restrict__ Wout,
                                                const float* __restrict__ aso,
                                                const float* __restrict__ ado) {
    int gw = (blockIdx.x * blockDim.x + threadIdx.x) >> 5;
    if (gw >= N_NODES) return;
    int n = gw;
    int lane = threadIdx.x & 31;
    int eg = lane >> 3;    // 0..3
    int lj = lane & 7;     // layer 0..7

    float aldj = g_ald[n * 8 + lj];

    float acc[8];
#pragma unroll
    for (int f = 0; f < 8; f++) acc[f] = 0.f;
    float sum = 0.f;

    int p0 = g_off[n], p1 = g_off[n + 1];
    for (int p = p0 + eg; p < p1 + 3; p += 4) {   // rounded up; masked
        bool valid = p < p1;
        int s = valid ? __ldg(&g_esrc[p]) : 0;
        float als = g_als[s * 8 + lj];
        uint4 h = *(const uint4*)&g_Hh[(size_t)s * 64 + lj * 8];
        float ev = als + aldj;
        ev = (ev > 0.f) ? ev : NEG_SLOPE * ev;
        float w = valid ? __expf(ev) : 0.f;
        sum += w;
        float2 f0 = h2f2(h.x), f1 = h2f2(h.y), f2 = h2f2(h.z), f3 = h2f2(h.w);
        acc[0] = fmaf(w, f0.x, acc[0]);
        acc[1] = fmaf(w, f0.y, acc[1]);
        acc[2] = fmaf(w, f1.x, acc[2]);
        acc[3] = fmaf(w, f1.y, acc[3]);
        acc[4] = fmaf(w, f2.x, acc[4]);
        acc[5] = fmaf(w, f2.y, acc[5]);
        acc[6] = fmaf(w, f3.x, acc[6]);
        acc[7] = fmaf(w, f3.y, acc[7]);
    }

    // reduce across edge-groups (lane bits 3,4), layer kept
    sum += __shfl_xor_sync(0xffffffffu, sum, 8);
    sum += __shfl_xor_sync(0xffffffffu, sum, 16);
#pragma unroll
    for (int f = 0; f < 8; f++) {
        acc[f] += __shfl_xor_sync(0xffffffffu, acc[f], 8);
        acc[f] += __shfl_xor_sync(0xffffffffu, acc[f], 16);
    }

    // per-layer normalize + bias, then cross-layer butterfly (lane bits 0..2)
    float r = 1.f / sum;
    float tot[8];
#pragma unroll
    for (int f = 0; f < 8; f++) tot[f] = acc[f] * r + bias_h[lj * 8 + f];
#pragma unroll
    for (int o = 1; o < 8; o <<= 1)
#pragma unroll
        for (int f = 0; f < 8; f++)
            tot[f] += __shfl_xor_sync(0xffffffffu, tot[f], o);

    float h2[8];
#pragma unroll
    for (int f = 0; f < 8; f++) {
        float v = tot[f] * 0.125f;
        h2[f] = (v > 0.f) ? v : (__expf(v) - 1.f);
    }
    // lane lj computes h3 cols lj and lj+8
    float c0 = 0.f, c1 = 0.f;
#pragma unroll
    for (int f = 0; f < 8; f++) {
        c0 = fmaf(h2[f], Wout[f * 16 + lj], c0);
        c1 = fmaf(h2[f], Wout[f * 16 + lj + 8], c1);
    }
    if (eg == 0) {
        g_h3h[(size_t)n * 16 + lj]     = __float2half(c0);
        g_h3h[(size_t)n * 16 + lj + 8] = __float2half(c1);
    }
    float ss = c0 * aso[lj] + c1 * aso[lj + 8];
    float dd = c0 * ado[lj] + c1 * ado[lj + 8];
#pragma unroll
    for (int o = 1; o < 8; o <<= 1) {
        ss += __shfl_xor_sync(0xffffffffu, ss, o);
        dd += __shfl_xor_sync(0xffffffffu, dd, o);
    }
    if (lane == 0) {
        g_al2s[n] = ss;
        g_al2d[n] = dd;
    }
}

// ---------------- layer 2: warp per node, 16 edges x 2 lanes --------------------
__global__ __launch_bounds__(256) void k_edge2w(const float* __restrict__ bias_o,
                                                float* __restrict__ out) {
    int gw = (blockIdx.x * blockDim.x + threadIdx.x) >> 5;
    if (gw >= N_NODES) return;
    int n = gw;
    int lane = threadIdx.x & 31;
    int eg = lane >> 1;    // 0..15
    int half = lane & 1;

    float al2d = g_al2d[n];

    float acc[8];
#pragma unroll
    for (int f = 0; f < 8; f++) acc[f] = 0.f;
    float sum = 0.f;

    int p0 = g_off[n], p1 = g_off[n + 1];
    for (int p = p0 + eg; p < p1 + 15; p += 16) {
        bool valid = p < p1;
        int s = valid ? __ldg(&g_esrc[p]) : 0;
        float l2 = g_al2s[s];
        uint4 h = *(const uint4*)&g_h3h[(size_t)s * 16 + half * 8];
        float tv = l2 + al2d;
        tv = (tv > 0.f) ? tv : NEG_SLOPE * tv;
        float w = valid ? __expf(tv) : 0.f;
        if (half == 0) sum += w;
        float2 f0 = h2f2(h.x), f1 = h2f2(h.y), f2 = h2f2(h.z), f3 = h2f2(h.w);
        acc[0] = fmaf(w, f0.x, acc[0]);
        acc[1] = fmaf(w, f0.y, acc[1]);
        acc[2] = fmaf(w, f1.x, acc[2]);
        acc[3] = fmaf(w, f1.y, acc[3]);
        acc[4] = fmaf(w, f2.x, acc[4]);
        acc[5] = fmaf(w, f2.y, acc[5]);
        acc[6] = fmaf(w, f3.x, acc[6]);
        acc[7] = fmaf(w, f3.y, acc[7]);
    }

    // sum: butterfly over all lanes (only half==0 contributed)
#pragma unroll
    for (int o = 1; o < 32; o <<= 1)
        sum += __shfl_xor_sync(0xffffffffu, sum, o);
    // acc: reduce across edge-groups (bits 1..4), keep half bit
#pragma unroll
    for (int f = 0; f < 8; f++) {
        acc[f] += __shfl_xor_sync(0xffffffffu, acc[f], 2);
        acc[f] += __shfl_xor_sync(0xffffffffu, acc[f], 4);
        acc[f] += __shfl_xor_sync(0xffffffffu, acc[f], 8);
        acc[f] += __shfl_xor_sync(0xffffffffu, acc[f], 16);
    }

    if (eg == 0) {
        float rs = 1.f / sum;
        float o8[8];
#pragma unroll
        for (int c = 0; c < 8; c++) o8[c] = acc[c] * rs + bias_o[half * 8 + c];
        float m = o8[0];
#pragma unroll
        for (int c = 1; c < 8; c++) m = fmaxf(m, o8[c]);
        m = fmaxf(m, __shfl_xor_sync(0xffffffffu, m, 1));
        float se = 0.f;
#pragma unroll
        for (int c = 0; c < 8; c++) se += __expf(o8[c] - m);
        se += __shfl_xor_sync(0xffffffffu, se, 1);
        float lse = __logf(se);
        float4* Or = (float4*)&out[(size_t)n * 16 + half * 8];
        Or[0] = make_float4(o8[0] - m - lse, o8[1] - m - lse, o8[2] - m - lse, o8[3] - m - lse);
        Or[1] = make_float4(o8[4] - m - lse, o8[5] - m - lse, o8[6] - m - lse, o8[7] - m - lse);
    }
}

// ---------------- launch ---------------------------------------------------------
#define GEMM_SMEM (GROWS * APAD * 2 + 64 * WT_K * 2)

extern "C" void kernel_launch(void* const* d_in, const int* in_sizes, int n_in,
                              void* d_out, int out_size) {
    const float* x    = (const float*)d_in[0];
    const void*  ei   = d_in[1];
    const float* Wh   = (const float*)d_in[2];
    const float* asrc = (const float*)d_in[3];
    const float* adst = (const float*)d_in[4];
    const float* bh   = (const float*)d_in[5];
    const float* Wout = (const float*)d_in[6];
    const float* aso  = (const float*)d_in[7];
    const float* ado  = (const float*)d_in[8];
    const float* bo   = (const float*)d_in[9];
    float*       out  = (float*)d_out;

    static int smem_set = 0;
    if (!smem_set) {
        cudaFuncSetAttribute(k_gemm, cudaFuncAttributeMaxDynamicSharedMemorySize, GEMM_SMEM);
        smem_set = 1;
    }

    cudaStream_t s2;
    cudaStreamCreateWithFlags(&s2, cudaStreamNonBlocking);
    cudaEvent_t evA, evB;
    cudaEventCreateWithFlags(&evA, cudaEventDisableTiming);
    cudaEventCreateWithFlags(&evB, cudaEventDisableTiming);

    cudaEventRecord(evA, 0);
    cudaStreamWaitEvent(s2, evA, 0);

    // --- side stream: edge prep + CSR ---
    void* p_deg;
    cudaGetSymbolAddress(&p_deg, g_deg);
    cudaMemsetAsync(p_deg, 0, sizeof(int) * N_NODES, s2);
    k_detect<<<1, 1, 0, s2>>>((const int*)ei);
    k_prep_edges<<<(ET + 255) / 256, 256, 0, s2>>>(ei);
    k_scan1<<<NPART, 1024, 0, s2>>>();
    k_scan2<<<1, 32, 0, s2>>>();
    k_scan3<<<(N_NODES + 255) / 256, 256, 0, s2>>>();
    k_scatter<<<(ET + 255) / 256, 256, 0, s2>>>();
    cudaEventRecord(evB, s2);

    // --- main stream: weights + tensor-core GEMM ---
    k_prep_w<<<(64 * DIN + 255) / 256, 256>>>(Wh);
    k_gemm<<<(N_NODES + GROWS - 1) / GROWS, 256, GEMM_SMEM>>>(x, asrc, adst);

    // join, then warp-per-node edge passes
    cudaStreamWaitEvent(0, evB, 0);
    k_edge1w<<<((size_t)N_NODES * 32 + 255) / 256, 256>>>(bh, Wout, aso, ado);
    k_edge2w<<<((size_t)N_NODES * 32 + 255) / 256, 256>>>(bo, out);
}

// round 9
// speedup vs baseline: 1.2127x; 1.2127x over previous
#include <cuda_runtime.h>
#include <cuda_fp16.h>
#include <math.h>

#define N_NODES 100000
#define DIN     512
#define NE      1600000
#define ET      (NE + N_NODES)   // edges + self loops
#define NEG_SLOPE 0.2f
#define NPART   ((N_NODES + 1023) / 1024)
#define WT_K    520              // padded k stride

// ---------------- scratch (device globals) -------------------------------------
__device__ __align__(128) __half g_Wt[64 * WT_K];              // W^T as half [n][k]
__device__ __align__(128) __half g_Hh[(size_t)N_NODES * 64];   // fp16 messages L1
__device__ __align__(128) float  g_als[N_NODES * 8];
__device__ __align__(128) float  g_ald[N_NODES * 8];
__device__ __align__(128) __half g_h3h[(size_t)N_NODES * 16];  // fp16 messages L2
__device__ __align__(128) float  g_al2s[N_NODES];
__device__ __align__(128) float  g_al2d[N_NODES];
__device__ int g_src[ET];
__device__ int g_dst[ET];
__device__ int g_esrc[ET];
__device__ int g_deg[N_NODES];
__device__ int g_off[N_NODES + 1];
__device__ int g_cur[N_NODES];
__device__ int g_part[NPART];
__device__ int g_is64;

__device__ __forceinline__ float2 h2f2(unsigned u) {
    __half2 h = *reinterpret_cast<const __half2*>(&u);
    return __half22float2(h);
}

// ---------------- edge-index dtype detection (JAX x64-off downcast) ------------
__global__ void k_detect(const int* __restrict__ ei32) {
    int allzero = 1;
    for (int i = 0; i < 128; i++)
        if (ei32[2 * i + 1] != 0) { allzero = 0; break; }
    g_is64 = allzero;
}

// prep + degree count fused
__global__ void k_prep_edges(const void* __restrict__ ei) {
    int e = blockIdx.x * blockDim.x + threadIdx.x;
    if (e >= ET) return;
    int s, d;
    if (e < NE) {
        if (g_is64) {
            const long long* p = (const long long*)ei;
            s = (int)p[e];
            d = (int)p[(size_t)NE + e];
        } else {
            const int* p = (const int*)ei;
            s = p[e];
            d = p[NE + e];
        }
        s = min(max(s, 0), N_NODES - 1);
        d = min(max(d, 0), N_NODES - 1);
    } else {
        s = e - NE;
        d = e - NE;
    }
    g_src[e] = s;
    g_dst[e] = d;
    atomicAdd(&g_deg[d], 1);
}

// g_Wt[n][k] = (half) W_hidden[n/8][k][n%8]
__global__ void k_prep_w(const float* __restrict__ Wh) {
    int i = blockIdx.x * blockDim.x + threadIdx.x;
    if (i >= 64 * DIN) return;
    int n = i >> 9, k = i & 511;
    int l = n >> 3, f = n & 7;
    g_Wt[n * WT_K + k] = __float2half(Wh[(size_t)l * (DIN * 8) + k * 8 + f]);
}

// ---------------- CSR build: scan + scatter --------------------------------------
__global__ __launch_bounds__(1024) void k_scan1() {
    __shared__ int wsum[32];
    int t = threadIdx.x, b = blockIdx.x;
    int i = b * 1024 + t;
    int v = (i < N_NODES) ? g_deg[i] : 0;
    int x = v;
    int lane = t & 31, w = t >> 5;
#pragma unroll
    for (int o = 1; o < 32; o <<= 1) {
        int y = __shfl_up_sync(0xffffffffu, x, o);
        if (lane >= o) x += y;
    }
    if (lane == 31) wsum[w] = x;
    __syncthreads();
    if (t < 32) {
        int y = wsum[t];
#pragma unroll
        for (int o = 1; o < 32; o <<= 1) {
            int z = __shfl_up_sync(0xffffffffu, y, o);
            if (t >= o) y += z;
        }
        wsum[t] = y;
    }
    __syncthreads();
    int excl = x - v + (w > 0 ? wsum[w - 1] : 0);
    if (i < N_NODES) g_off[i] = excl;
    if (t == 0) g_part[b] = wsum[31];
}

__global__ void k_scan2() {
    int t = threadIdx.x;
    int base = 0;
    for (int s = 0; s < NPART; s += 32) {
        int i = s + t;
        int v = (i < NPART) ? g_part[i] : 0;
        int x = v;
#pragma unroll
        for (int o = 1; o < 32; o <<= 1) {
            int y = __shfl_up_sync(0xffffffffu, x, o);
            if (t >= o) x += y;
        }
        if (i < NPART) g_part[i] = base + x - v;
        base += __shfl_sync(0xffffffffu, x, 31);
    }
}

__global__ void k_scan3() {
    int i = blockIdx.x * blockDim.x + threadIdx.x;
    if (i >= N_NODES) return;
    int o = g_off[i] + g_part[i >> 10];
    g_off[i] = o;
    g_cur[i] = o;
    if (i == 0) g_off[N_NODES] = ET;
}

__global__ void k_scatter() {
    int e = blockIdx.x * blockDim.x + threadIdx.x;
    if (e >= ET) return;
    int d = g_dst[e];
    int pos = atomicAdd(&g_cur[d], 1);
    g_esrc[pos] = g_src[e];
}

// ---------------- tensor-core GEMM: H = x @ W (fp16 HMMA, fp32 acc) -------------
#define GROWS 128
#define AKC   64
#define APAD  72
__global__ __launch_bounds__(256) void k_gemm(const float* __restrict__ x,
                                              const float* __restrict__ asrc,
                                              const float* __restrict__ adst) {
    extern __shared__ char smem[];
    __half* As = (__half*)smem;                       // [128][72]
    __half* Ws = (__half*)(smem + GROWS * APAD * 2);  // [64][520]

    const int t = threadIdx.x;
    const int w = t >> 5;
    const int l = t & 31;
    const int row0 = blockIdx.x * GROWS;
    const int g = l >> 2;
    const int q = l & 3;

    {
        const uint4* src = (const uint4*)g_Wt;
#pragma unroll
        for (int i = 0; i < 16; i++) {
            int idx = i * 256 + t;
            int r = idx >> 6, c = idx & 63;
            *(uint4*)&Ws[r * WT_K + c * 8] = src[(r * WT_K + c * 8) >> 3];
        }
    }

    float acc[8][4];
#pragma unroll
    for (int n = 0; n < 8; n++)
#pragma unroll
        for (int j = 0; j < 4; j++) acc[n][j] = 0.f;

    const int arow = (l & 7) + ((l & 8) ? 8 : 0);
    const int acol = (l & 16) ? 8 : 0;

    __syncthreads();

    for (int kt = 0; kt < DIN; kt += AKC) {
#pragma unroll
        for (int i = 0; i < 8; i++) {
            int idx = i * 256 + t;
            int r = idx >> 4, c4 = idx & 15;
            int rg = row0 + r; if (rg >= N_NODES) rg = N_NODES - 1;
            float4 v = *(const float4*)&x[(size_t)rg * DIN + kt + c4 * 4];
            __half2* dst = (__half2*)&As[r * APAD + c4 * 4];
            dst[0] = __floats2half2_rn(v.x, v.y);
            dst[1] = __floats2half2_rn(v.z, v.w);
        }
        __syncthreads();

#pragma unroll
        for (int k0 = 0; k0 < AKC; k0 += 16) {
            unsigned a0, a1, a2, a3;
            unsigned aaddr = __cvta_generic_to_shared(
                &As[(w * 16 + arow) * APAD + k0 + acol]);
            asm volatile("ldmatrix.sync.aligned.m8n8.x4.shared.b16 {%0,%1,%2,%3}, [%4];"
                         : "=r"(a0), "=r"(a1), "=r"(a2), "=r"(a3) : "r"(aaddr));
            int kg = kt + k0;
#pragma unroll
            for (int nt = 0; nt < 8; nt++) {
                int n = nt * 8 + g;
                unsigned b0 = *(const unsigned*)&Ws[n * WT_K + kg + 2 * q];
                unsigned b1 = *(const unsigned*)&Ws[n * WT_K + kg + 8 + 2 * q];
                asm volatile(
                    "mma.sync.aligned.m16n8k16.row.col.f32.f16.f16.f32 "
                    "{%0,%1,%2,%3}, {%4,%5,%6,%7}, {%8,%9}, {%0,%1,%2,%3};"
                    : "+f"(acc[nt][0]), "+f"(acc[nt][1]), "+f"(acc[nt][2]), "+f"(acc[nt][3])
                    : "r"(a0), "r"(a1), "r"(a2), "r"(a3), "r"(b0), "r"(b1));
            }
        }
        __syncthreads();
    }

    int row_lo = row0 + w * 16 + g;
    int row_hi = row_lo + 8;
#pragma unroll
    for (int nt = 0; nt < 8; nt++) {
        int c0 = nt * 8 + 2 * q, c1 = c0 + 1;
        if (row_lo < N_NODES)
            *(__half2*)&g_Hh[(size_t)row_lo * 64 + c0] = __floats2half2_rn(acc[nt][0], acc[nt][1]);
        if (row_hi < N_NODES)
            *(__half2*)&g_Hh[(size_t)row_hi * 64 + c0] = __floats2half2_rn(acc[nt][2], acc[nt][3]);
        float as0 = asrc[c0], as1 = asrc[c1], ad0 = adst[c0], ad1 = adst[c1];
        float psl_s = acc[nt][0] * as0 + acc[nt][1] * as1;
        float psl_d = acc[nt][0] * ad0 + acc[nt][1] * ad1;
        float psh_s = acc[nt][2] * as0 + acc[nt][3] * as1;
        float psh_d = acc[nt][2] * ad0 + acc[nt][3] * ad1;
        psl_s += __shfl_xor_sync(0xffffffffu, psl_s, 1);
        psl_s += __shfl_xor_sync(0xffffffffu, psl_s, 2);
        psl_d += __shfl_xor_sync(0xffffffffu, psl_d, 1);
        psl_d += __shfl_xor_sync(0xffffffffu, psl_d, 2);
        psh_s += __shfl_xor_sync(0xffffffffu, psh_s, 1);
        psh_s += __shfl_xor_sync(0xffffffffu, psh_s, 2);
        psh_d += __shfl_xor_sync(0xffffffffu, psh_d, 1);
        psh_d += __shfl_xor_sync(0xffffffffu, psh_d, 2);
        if (q == 0) {
            if (row_lo < N_NODES) { g_als[row_lo * 8 + nt] = psl_s; g_ald[row_lo * 8 + nt] = psl_d; }
            if (row_hi < N_NODES) { g_als[row_hi * 8 + nt] = psh_s; g_ald[row_hi * 8 + nt] = psh_d; }
        }
    }
}

// ---------------- layer 1: 8 lanes per node, lane = layer -----------------------
// Loop length = deg. Per edge the group loads the whole 128B H row in ONE LDG.128
// (1 line), als as one 32B chunk, esrc broadcast. No per-edge reductions.
// 800000 threads = 25000 full warps x 4 nodes: no guards needed.
__global__ __launch_bounds__(256) void k_edge1v(const float* __restrict__ bias_h,
                                                const float* __restrict__ Wout,
                                                const float* __restrict__ aso,
                                                const float* __restrict__ ado) {
    int tid = blockIdx.x * blockDim.x + threadIdx.x;
    int n = tid >> 3;          // node
    int lj = tid & 7;          // layer
    int lane = threadIdx.x & 31;

    float aldj = g_ald[n * 8 + lj];

    float acc[8];
#pragma unroll
    for (int f = 0; f < 8; f++) acc[f] = 0.f;
    float sum = 0.f;

    int p0 = g_off[n], p1 = g_off[n + 1];
    for (int p = p0; p < p1; p++) {
        int s = __ldg(&g_esrc[p]);                       // broadcast in group
        float als = g_als[s * 8 + lj];                   // group: 32B chunk
        uint4 h = *(const uint4*)&g_Hh[(size_t)s * 64 + lj * 8];  // group: 128B row
        float ev = als + aldj;
        ev = (ev > 0.f) ? ev : NEG_SLOPE * ev;
        float w = __expf(ev);
        sum += w;
        float2 f0 = h2f2(h.x), f1 = h2f2(h.y), f2 = h2f2(h.z), f3 = h2f2(h.w);
        acc[0] = fmaf(w, f0.x, acc[0]);
        acc[1] = fmaf(w, f0.y, acc[1]);
        acc[2] = fmaf(w, f1.x, acc[2]);
        acc[3] = fmaf(w, f1.y, acc[3]);
        acc[4] = fmaf(w, f2.x, acc[4]);
        acc[5] = fmaf(w, f2.y, acc[5]);
        acc[6] = fmaf(w, f3.x, acc[6]);
        acc[7] = fmaf(w, f3.y, acc[7]);
    }

    // per-layer normalize + bias, then cross-layer butterfly (bits 0..2 of lane)
    float r = 1.f / sum;
    float tot[8];
#pragma unroll
    for (int f = 0; f < 8; f++) tot[f] = acc[f] * r + bias_h[lj * 8 + f];
#pragma unroll
    for (int o = 1; o < 8; o <<= 1)
#pragma unroll
        for (int f = 0; f < 8; f++)
            tot[f] += __shfl_xor_sync(0xffffffffu, tot[f], o);

    float h2[8];
#pragma unroll
    for (int f = 0; f < 8; f++) {
        float v = tot[f] * 0.125f;
        h2[f] = (v > 0.f) ? v : (__expf(v) - 1.f);
    }
    // lane lj computes h3 cols lj and lj+8
    float c0 = 0.f, c1 = 0.f;
#pragma unroll
    for (int f = 0; f < 8; f++) {
        c0 = fmaf(h2[f], Wout[f * 16 + lj], c0);
        c1 = fmaf(h2[f], Wout[f * 16 + lj + 8], c1);
    }
    g_h3h[(size_t)n * 16 + lj]     = __float2half(c0);
    g_h3h[(size_t)n * 16 + lj + 8] = __float2half(c1);

    float ss = c0 * aso[lj] + c1 * aso[lj + 8];
    float dd = c0 * ado[lj] + c1 * ado[lj + 8];
#pragma unroll
    for (int o = 1; o < 8; o <<= 1) {
        ss += __shfl_xor_sync(0xffffffffu, ss, o);
        dd += __shfl_xor_sync(0xffffffffu, dd, o);
    }
    if (lj == 0) {
        g_al2s[n] = ss;
        g_al2d[n] = dd;
    }
    (void)lane;
}

// ---------------- layer 2: 4 lanes per node, lane = feature-quad ----------------
// 400000 threads = 12500 full warps x 8 nodes: no guards needed.
__global__ __launch_bounds__(128) void k_edge2v(const float* __restrict__ bias_o,
                                                float* __restrict__ out) {
    int tid = blockIdx.x * blockDim.x + threadIdx.x;
    int n = tid >> 2;          // node
    int q4 = tid & 3;          // feature quad (cols 4q4..4q4+3)

    float al2d = g_al2d[n];

    float acc[4] = {0.f, 0.f, 0.f, 0.f};
    float sum = 0.f;

    int p0 = g_off[n], p1 = g_off[n + 1];
    for (int p = p0; p < p1; p++) {
        int s = __ldg(&g_esrc[p]);                       // broadcast in quad
        float l2 = g_al2s[s];                            // broadcast in quad
        uint2 h = *(const uint2*)&g_h3h[(size_t)s * 16 + q4 * 4];  // quad: 32B row
        float tv = l2 + al2d;
        tv = (tv > 0.f) ? tv : NEG_SLOPE * tv;
        float w = __expf(tv);
        sum += w;                                        // identical across quad
        float2 f0 = h2f2(h.x), f1 = h2f2(h.y);
        acc[0] = fmaf(w, f0.x, acc[0]);
        acc[1] = fmaf(w, f0.y, acc[1]);
        acc[2] = fmaf(w, f1.x, acc[2]);
        acc[3] = fmaf(w, f1.y, acc[3]);
    }

    float rs = 1.f / sum;
    float o4[4];
#pragma unroll
    for (int c = 0; c < 4; c++) o4[c] = acc[c] * rs + bias_o[q4 * 4 + c];

    // log_softmax across the 16 cols: butterfly over quad (bits 0..1)
    float m = fmaxf(fmaxf(o4[0], o4[1]), fmaxf(o4[2], o4[3]));
    m = fmaxf(m, __shfl_xor_sync(0xffffffffu, m, 1));
    m = fmaxf(m, __shfl_xor_sync(0xffffffffu, m, 2));
    float se = __expf(o4[0] - m) + __expf(o4[1] - m) + __expf(o4[2] - m) + __expf(o4[3] - m);
    se += __shfl_xor_sync(0xffffffffu, se, 1);
    se += __shfl_xor_sync(0xffffffffu, se, 2);
    float lse = __logf(se);
    *(float4*)&out[(size_t)n * 16 + q4 * 4] =
        make_float4(o4[0] - m - lse, o4[1] - m - lse, o4[2] - m - lse, o4[3] - m - lse);
}

// ---------------- launch ---------------------------------------------------------
#define GEMM_SMEM (GROWS * APAD * 2 + 64 * WT_K * 2)

extern "C" void kernel_launch(void* const* d_in, const int* in_sizes, int n_in,
                              void* d_out, int out_size) {
    const float* x    = (const float*)d_in[0];
    const void*  ei   = d_in[1];
    const float* Wh   = (const float*)d_in[2];
    const float* asrc = (const float*)d_in[3];
    const float* adst = (const float*)d_in[4];
    const float* bh   = (const float*)d_in[5];
    const float* Wout = (const float*)d_in[6];
    const float* aso  = (const float*)d_in[7];
    const float* ado  = (const float*)d_in[8];
    const float* bo   = (const float*)d_in[9];
    float*       out  = (float*)d_out;

    static int smem_set = 0;
    if (!smem_set) {
        cudaFuncSetAttribute(k_gemm, cudaFuncAttributeMaxDynamicSharedMemorySize, GEMM_SMEM);
        smem_set = 1;
    }

    cudaStream_t s2;
    cudaStreamCreateWithFlags(&s2, cudaStreamNonBlocking);
    cudaEvent_t evA, evB;
    cudaEventCreateWithFlags(&evA, cudaEventDisableTiming);
    cudaEventCreateWithFlags(&evB, cudaEventDisableTiming);

    cudaEventRecord(evA, 0);
    cudaStreamWaitEvent(s2, evA, 0);

    // --- side stream: edge prep + CSR ---
    void* p_deg;
    cudaGetSymbolAddress(&p_deg, g_deg);
    cudaMemsetAsync(p_deg, 0, sizeof(int) * N_NODES, s2);
    k_detect<<<1, 1, 0, s2>>>((const int*)ei);
    k_prep_edges<<<(ET + 255) / 256, 256, 0, s2>>>(ei);
    k_scan1<<<NPART, 1024, 0, s2>>>();
    k_scan2<<<1, 32, 0, s2>>>();
    k_scan3<<<(N_NODES + 255) / 256, 256, 0, s2>>>();
    k_scatter<<<(ET + 255) / 256, 256, 0, s2>>>();
    cudaEventRecord(evB, s2);

    // --- main stream: weights + tensor-core GEMM ---
    k_prep_w<<<(64 * DIN + 255) / 256, 256>>>(Wh);
    k_gemm<<<(N_NODES + GROWS - 1) / GROWS, 256, GEMM_SMEM>>>(x, asrc, adst);

    // join, then lane-group-per-node edge passes
    cudaStreamWaitEvent(0, evB, 0);
    k_edge1v<<<(N_NODES * 8) / 256, 256>>>(bh, Wout, aso, ado);
    k_edge2v<<<(N_NODES * 4) / 128, 128>>>(bo, out);
}

// round 10
// speedup vs baseline: 1.2911x; 1.0646x over previous
#include <cuda_runtime.h>
#include <cuda_fp16.h>
#include <math.h>

#define N_NODES 100000
#define DIN     512
#define NE      1600000
#define ET      (NE + N_NODES)   // edges + self loops
#define NEG_SLOPE 0.2f
#define NPART   ((N_NODES + 1023) / 1024)   // 98 blocks, all resident on 148 SMs
#define WT_K    520              // padded k stride

// ---------------- scratch (device globals) -------------------------------------
__device__ __align__(128) __half g_Wt[64 * WT_K];              // W^T as half [n][k]
__device__ __align__(128) __half g_Hh[(size_t)N_NODES * 64];   // fp16 messages L1
__device__ __align__(128) float  g_ald[N_NODES * 8];
__device__ __align__(128) __half g_h3h[(size_t)N_NODES * 16];  // fp16 messages L2
__device__ __align__(128) float  g_al2s[N_NODES];
__device__ __align__(128) float  g_al2d[N_NODES];
__device__ int g_esrc[ET];
__device__ int g_deg[N_NODES + NPART];   // [0,N): degrees; [N, N+NPART): scan totals+flag (tot+1)
__device__ int g_off[N_NODES + 1];
__device__ int g_cur[N_NODES];

__device__ __forceinline__ float2 h2f2(unsigned u) {
    __half2 h = *reinterpret_cast<const __half2*>(&u);
    return __half22float2(h);
}

// Per-block edge-index dtype detection (JAX x64-off downcast): for genuine int64
// node ids in [0,N) every odd 32-bit word is 0; for int32 random ids P(64 zeros)~0.
__device__ __forceinline__ int detect_is64(const int* ei32) {
    int allzero = 1;
#pragma unroll 8
    for (int i = 0; i < 64; i++)
        if (__ldg(&ei32[2 * i + 1]) != 0) { allzero = 0; break; }
    return allzero;
}

__device__ __forceinline__ void decode_edge(const void* ei, int is64, int e,
                                            int* s, int* d) {
    if (e < NE) {
        int sv, dv;
        if (is64) {
            const long long* p = (const long long*)ei;
            sv = (int)p[e];
            dv = (int)p[(size_t)NE + e];
        } else {
            const int* p = (const int*)ei;
            sv = p[e];
            dv = p[NE + e];
        }
        *s = min(max(sv, 0), N_NODES - 1);
        *d = min(max(dv, 0), N_NODES - 1);
    } else {
        *s = e - NE;
        *d = e - NE;
    }
}

// ---------------- degree count (reads edge_index directly) ----------------------
__global__ void k_count(const void* __restrict__ ei) {
    int is64 = detect_is64((const int*)ei);
    int e = blockIdx.x * blockDim.x + threadIdx.x;
    if (e >= ET) return;
    int s, d;
    decode_edge(ei, is64, e, &s, &d);
    atomicAdd(&g_deg[d], 1);
}

// ---------------- single-launch exclusive scan (decoupled lookback) -------------
// 98 blocks x 1024; all blocks resident, so polling lower blocks is deadlock-free.
__global__ __launch_bounds__(1024) void k_scan() {
    __shared__ int wsum[32];
    __shared__ int sbase;
    int t = threadIdx.x, b = blockIdx.x;
    if (t == 0) sbase = 0;
    int i = b * 1024 + t;
    int v = (i < N_NODES) ? g_deg[i] : 0;
    int x = v;
    int lane = t & 31, w = t >> 5;
#pragma unroll
    for (int o = 1; o < 32; o <<= 1) {
        int y = __shfl_up_sync(0xffffffffu, x, o);
        if (lane >= o) x += y;
    }
    if (lane == 31) wsum[w] = x;
    __syncthreads();
    if (t < 32) {
        int y = wsum[t];
#pragma unroll
        for (int o = 1; o < 32; o <<= 1) {
            int z = __shfl_up_sync(0xffffffffu, y, o);
            if (t >= o) y += z;
        }
        wsum[t] = y;
    }
    __syncthreads();

    volatile int* bs = (volatile int*)&g_deg[N_NODES];
    if (t == 0) bs[b] = wsum[31] + 1;            // publish inclusive total (+1 flag)
    if (t < b) {                                  // lookback: poll lower blocks
        int pv;
        while ((pv = bs[t]) == 0) {}
        atomicAdd(&sbase, pv - 1);
    }
    __syncthreads();

    int excl = x - v + (w > 0 ? wsum[w - 1] : 0) + sbase;
    if (i < N_NODES) { g_off[i] = excl; g_cur[i] = excl; }
    if (b == 0 && t == 0) g_off[N_NODES] = ET;
}

// ---------------- scatter (re-decodes edge_index; src/dst arrays eliminated) ----
__global__ void k_scatter(const void* __restrict__ ei) {
    int is64 = detect_is64((const int*)ei);
    int e = blockIdx.x * blockDim.x + threadIdx.x;
    if (e >= ET) return;
    int s, d;
    decode_edge(ei, is64, e, &s, &d);
    int pos = atomicAdd(&g_cur[d], 1);
    g_esrc[pos] = s;
}

// g_Wt[n][k] = (half) W_hidden[n/8][k][n%8]
__global__ void k_prep_w(const float* __restrict__ Wh) {
    int i = blockIdx.x * blockDim.x + threadIdx.x;
    if (i >= 64 * DIN) return;
    int n = i >> 9, k = i & 511;
    int l = n >> 3, f = n & 7;
    g_Wt[n * WT_K + k] = __float2half(Wh[(size_t)l * (DIN * 8) + k * 8 + f]);
}

// ---------------- tensor-core GEMM: H = x @ W (fp16 HMMA, fp32 acc) -------------
#define GROWS 128
#define AKC   64
#define APAD  72
__global__ __launch_bounds__(256) void k_gemm(const float* __restrict__ x,
                                              const float* __restrict__ adst) {
    extern __shared__ char smem[];
    __half* As = (__half*)smem;                       // [128][72]
    __half* Ws = (__half*)(smem + GROWS * APAD * 2);  // [64][520]

    const int t = threadIdx.x;
    const int w = t >> 5;
    const int l = t & 31;
    const int row0 = blockIdx.x * GROWS;
    const int g = l >> 2;
    const int q = l & 3;

    {
        const uint4* src = (const uint4*)g_Wt;
#pragma unroll
        for (int i = 0; i < 16; i++) {
            int idx = i * 256 + t;
            int r = idx >> 6, c = idx & 63;
            *(uint4*)&Ws[r * WT_K + c * 8] = src[(r * WT_K + c * 8) >> 3];
        }
    }

    float acc[8][4];
#pragma unroll
    for (int n = 0; n < 8; n++)
#pragma unroll
        for (int j = 0; j < 4; j++) acc[n][j] = 0.f;

    const int arow = (l & 7) + ((l & 8) ? 8 : 0);
    const int acol = (l & 16) ? 8 : 0;

    __syncthreads();

    for (int kt = 0; kt < DIN; kt += AKC) {
#pragma unroll
        for (int i = 0; i < 8; i++) {
            int idx = i * 256 + t;
            int r = idx >> 4, c4 = idx & 15;
            int rg = row0 + r; if (rg >= N_NODES) rg = N_NODES - 1;
            float4 v = *(const float4*)&x[(size_t)rg * DIN + kt + c4 * 4];
            __half2* dst = (__half2*)&As[r * APAD + c4 * 4];
            dst[0] = __floats2half2_rn(v.x, v.y);
            dst[1] = __floats2half2_rn(v.z, v.w);
        }
        __syncthreads();

#pragma unroll
        for (int k0 = 0; k0 < AKC; k0 += 16) {
            unsigned a0, a1, a2, a3;
            unsigned aaddr = __cvta_generic_to_shared(
                &As[(w * 16 + arow) * APAD + k0 + acol]);
            asm volatile("ldmatrix.sync.aligned.m8n8.x4.shared.b16 {%0,%1,%2,%3}, [%4];"
                         : "=r"(a0), "=r"(a1), "=r"(a2), "=r"(a3) : "r"(aaddr));
            int kg = kt + k0;
#pragma unroll
            for (int nt = 0; nt < 8; nt++) {
                int n = nt * 8 + g;
                unsigned b0 = *(const unsigned*)&Ws[n * WT_K + kg + 2 * q];
                unsigned b1 = *(const unsigned*)&Ws[n * WT_K + kg + 8 + 2 * q];
                asm volatile(
                    "mma.sync.aligned.m16n8k16.row.col.f32.f16.f16.f32 "
                    "{%0,%1,%2,%3}, {%4,%5,%6,%7}, {%8,%9}, {%0,%1,%2,%3};"
                    : "+f"(acc[nt][0]), "+f"(acc[nt][1]), "+f"(acc[nt][2]), "+f"(acc[nt][3])
                    : "r"(a0), "r"(a1), "r"(a2), "r"(a3), "r"(b0), "r"(b1));
            }
        }
        __syncthreads();
    }

    int row_lo = row0 + w * 16 + g;
    int row_hi = row_lo + 8;
#pragma unroll
    for (int nt = 0; nt < 8; nt++) {
        int c0 = nt * 8 + 2 * q, c1 = c0 + 1;
        if (row_lo < N_NODES)
            *(__half2*)&g_Hh[(size_t)row_lo * 64 + c0] = __floats2half2_rn(acc[nt][0], acc[nt][1]);
        if (row_hi < N_NODES)
            *(__half2*)&g_Hh[(size_t)row_hi * 64 + c0] = __floats2half2_rn(acc[nt][2], acc[nt][3]);
        // only dst logits needed globally (src logits computed inline in edge1)
        float ad0 = adst[c0], ad1 = adst[c1];
        float psl_d = acc[nt][0] * ad0 + acc[nt][1] * ad1;
        float psh_d = acc[nt][2] * ad0 + acc[nt][3] * ad1;
        psl_d += __shfl_xor_sync(0xffffffffu, psl_d, 1);
        psl_d += __shfl_xor_sync(0xffffffffu, psl_d, 2);
        psh_d += __shfl_xor_sync(0xffffffffu, psh_d, 1);
        psh_d += __shfl_xor_sync(0xffffffffu, psh_d, 2);
        if (q == 0) {
            if (row_lo < N_NODES) g_ald[row_lo * 8 + nt] = psl_d;
            if (row_hi < N_NODES) g_ald[row_hi * 8 + nt] = psh_d;
        }
    }
}

// ---------------- layer 1: 8 lanes per node, lane = layer -----------------------
// al_src computed inline from the H row already being loaded (8 FMAs) -> no als
// gather. Per edge the group touches ONE random 128B line (the H row).
__global__ __launch_bounds__(256) void k_edge1v(const float* __restrict__ asrc,
                                                const float* __restrict__ bias_h,
                                                const float* __restrict__ Wout,
                                                const float* __restrict__ aso,
                                                const float* __restrict__ ado) {
    int tid = blockIdx.x * blockDim.x + threadIdx.x;
    int n = tid >> 3;          // node
    int lj = tid & 7;          // layer

    float aldj = g_ald[n * 8 + lj];
    float as[8];
#pragma unroll
    for (int f = 0; f < 8; f++) as[f] = asrc[lj * 8 + f];

    float acc[8];
#pragma unroll
    for (int f = 0; f < 8; f++) acc[f] = 0.f;
    float sum = 0.f;

    int p0 = g_off[n], p1 = g_off[n + 1];
    for (int p = p0; p < p1; p++) {
        int s = __ldg(&g_esrc[p]);                                // broadcast in group
        uint4 h = *(const uint4*)&g_Hh[(size_t)s * 64 + lj * 8];  // group: one 128B line
        float2 f0 = h2f2(h.x), f1 = h2f2(h.y), f2 = h2f2(h.z), f3 = h2f2(h.w);
        // inline al_src: dot(H[s, layer lj], asrc[layer lj])
        float als = f0.x * as[0] + f0.y * as[1] + f1.x * as[2] + f1.y * as[3]
                  + f2.x * as[4] + f2.y * as[5] + f3.x * as[6] + f3.y * as[7];
        float ev = als + aldj;
        ev = (ev > 0.f) ? ev : NEG_SLOPE * ev;
        float w = __expf(ev);
        sum += w;
        acc[0] = fmaf(w, f0.x, acc[0]);
        acc[1] = fmaf(w, f0.y, acc[1]);
        acc[2] = fmaf(w, f1.x, acc[2]);
        acc[3] = fmaf(w, f1.y, acc[3]);
        acc[4] = fmaf(w, f2.x, acc[4]);
        acc[5] = fmaf(w, f2.y, acc[5]);
        acc[6] = fmaf(w, f3.x, acc[6]);
        acc[7] = fmaf(w, f3.y, acc[7]);
    }

    // per-layer normalize + bias, then cross-layer butterfly (bits 0..2 of lane)
    float r = 1.f / sum;
    float tot[8];
#pragma unroll
    for (int f = 0; f < 8; f++) tot[f] = acc[f] * r + bias_h[lj * 8 + f];
#pragma unroll
    for (int o = 1; o < 8; o <<= 1)
#pragma unroll
        for (int f = 0; f < 8; f++)
            tot[f] += __shfl_xor_sync(0xffffffffu, tot[f], o);

    float h2[8];
#pragma unroll
    for (int f = 0; f < 8; f++) {
        float v = tot[f] * 0.125f;
        h2[f] = (v > 0.f) ? v : (__expf(v) - 1.f);
    }
    float c0 = 0.f, c1 = 0.f;
#pragma unroll
    for (int f = 0; f < 8; f++) {
        c0 = fmaf(h2[f], Wout[f * 16 + lj], c0);
        c1 = fmaf(h2[f], Wout[f * 16 + lj + 8], c1);
    }
    g_h3h[(size_t)n * 16 + lj]     = __float2half(c0);
    g_h3h[(size_t)n * 16 + lj + 8] = __float2half(c1);

    float ss = c0 * aso[lj] + c1 * aso[lj + 8];
    float dd = c0 * ado[lj] + c1 * ado[lj + 8];
#pragma unroll
    for (int o = 1; o < 8; o <<= 1) {
        ss += __shfl_xor_sync(0xffffffffu, ss, o);
        dd += __shfl_xor_sync(0xffffffffu, dd, o);
    }
    if (lj == 0) {
        g_al2s[n] = ss;
        g_al2d[n] = dd;
    }
}

// ---------------- layer 2: 4 lanes per node, lane = feature-quad ----------------
__global__ __launch_bounds__(128) void k_edge2v(const float* __restrict__ bias_o,
                                                float* __restrict__ out) {
    int tid = blockIdx.x * blockDim.x + threadIdx.x;
    int n = tid >> 2;          // node
    int q4 = tid & 3;          // feature quad (cols 4q4..4q4+3)

    float al2d = g_al2d[n];

    float acc[4] = {0.f, 0.f, 0.f, 0.f};
    float sum = 0.f;

    int p0 = g_off[n], p1 = g_off[n + 1];
    for (int p = p0; p < p1; p++) {
        int s = __ldg(&g_esrc[p]);                       // broadcast in quad
        float l2 = g_al2s[s];                            // broadcast in quad
        uint2 h = *(const uint2*)&g_h3h[(size_t)s * 16 + q4 * 4];
        float tv = l2 + al2d;
        tv = (tv > 0.f) ? tv : NEG_SLOPE * tv;
        float w = __expf(tv);
        sum += w;
        float2 f0 = h2f2(h.x), f1 = h2f2(h.y);
        acc[0] = fmaf(w, f0.x, acc[0]);
        acc[1] = fmaf(w, f0.y, acc[1]);
        acc[2] = fmaf(w, f1.x, acc[2]);
        acc[3] = fmaf(w, f1.y, acc[3]);
    }

    float rs = 1.f / sum;
    float o4[4];
#pragma unroll
    for (int c = 0; c < 4; c++) o4[c] = acc[c] * rs + bias_o[q4 * 4 + c];

    float m = fmaxf(fmaxf(o4[0], o4[1]), fmaxf(o4[2], o4[3]));
    m = fmaxf(m, __shfl_xor_sync(0xffffffffu, m, 1));
    m = fmaxf(m, __shfl_xor_sync(0xffffffffu, m, 2));
    float se = __expf(o4[0] - m) + __expf(o4[1] - m) + __expf(o4[2] - m) + __expf(o4[3] - m);
    se += __shfl_xor_sync(0xffffffffu, se, 1);
    se += __shfl_xor_sync(0xffffffffu, se, 2);
    float lse = __logf(se);
    *(float4*)&out[(size_t)n * 16 + q4 * 4] =
        make_float4(o4[0] - m - lse, o4[1] - m - lse, o4[2] - m - lse, o4[3] - m - lse);
}

// ---------------- launch ---------------------------------------------------------
#define GEMM_SMEM (GROWS * APAD * 2 + 64 * WT_K * 2)

extern "C" void kernel_launch(void* const* d_in, const int* in_sizes, int n_in,
                              void* d_out, int out_size) {
    const float* x    = (const float*)d_in[0];
    const void*  ei   = d_in[1];
    const float* Wh   = (const float*)d_in[2];
    const float* asrc = (const float*)d_in[3];
    const float* adst = (const float*)d_in[4];
    const float* bh   = (const float*)d_in[5];
    const float* Wout = (const float*)d_in[6];
    const float* aso  = (const float*)d_in[7];
    const float* ado  = (const float*)d_in[8];
    const float* bo   = (const float*)d_in[9];
    float*       out  = (float*)d_out;

    static int smem_set = 0;
    if (!smem_set) {
        cudaFuncSetAttribute(k_gemm, cudaFuncAttributeMaxDynamicSharedMemorySize, GEMM_SMEM);
        smem_set = 1;
    }

    cudaStream_t s2;
    cudaStreamCreateWithFlags(&s2, cudaStreamNonBlocking);
    cudaEvent_t evA, evB;
    cudaEventCreateWithFlags(&evA, cudaEventDisableTiming);
    cudaEventCreateWithFlags(&evB, cudaEventDisableTiming);

    cudaEventRecord(evA, 0);
    cudaStreamWaitEvent(s2, evA, 0);

    // --- side stream: degree count + scan + scatter (CSR) ---
    void* p_deg;
    cudaGetSymbolAddress(&p_deg, g_deg);
    cudaMemsetAsync(p_deg, 0, sizeof(int) * (N_NODES + NPART), s2);
    k_count<<<(ET + 255) / 256, 256, 0, s2>>>(ei);
    k_scan<<<NPART, 1024, 0, s2>>>();
    k_scatter<<<(ET + 255) / 256, 256, 0, s2>>>(ei);
    cudaEventRecord(evB, s2);

    // --- main stream: weights + tensor-core GEMM ---
    k_prep_w<<<(64 * DIN + 255) / 256, 256>>>(Wh);
    k_gemm<<<(N_NODES + GROWS - 1) / GROWS, 256, GEMM_SMEM>>>(x, adst);

    // join, then lane-group-per-node edge passes
    cudaStreamWaitEvent(0, evB, 0);
    k_edge1v<<<(N_NODES * 8) / 256, 256>>>(asrc, bh, Wout, aso, ado);
    k_edge2v<<<(N_NODES * 4) / 128, 128>>>(bo, out);
}

// round 11
// speedup vs baseline: 1.3111x; 1.0155x over previous
#include <cuda_runtime.h>
#include <cuda_fp16.h>
#include <math.h>

#define N_NODES 100000
#define DIN     512
#define NE      1600000
#define ET      (NE + N_NODES)   // edges + self loops
#define NEG_SLOPE 0.2f
#define NPART   ((N_NODES + 1023) / 1024)   // 98 blocks, all resident on 148 SMs
#define WT_K    520              // padded k stride

// ---------------- scratch (device globals) -------------------------------------
__device__ __align__(128) __half g_Wt[64 * WT_K];              // W^T as half [n][k]
__device__ __align__(128) __half g_Hh[(size_t)N_NODES * 64];   // fp16 messages L1
__device__ __align__(128) float  g_ald[N_NODES * 8];
__device__ __align__(128) __half g_h3h[(size_t)N_NODES * 16];  // fp16 messages L2
__device__ __align__(128) float  g_al2s[N_NODES];
__device__ __align__(128) float  g_al2d[N_NODES];
__device__ int g_esrc[ET];
__device__ int g_deg[N_NODES + NPART];   // [0,N): degrees; [N,+NPART): scan totals+1
__device__ int g_off[N_NODES + 1];
__device__ int g_cur[N_NODES];

__device__ __forceinline__ float2 h2f2(unsigned u) {
    __half2 h = *reinterpret_cast<const __half2*>(&u);
    return __half22float2(h);
}

// Per-block edge-index dtype detection (JAX x64-off downcast): for genuine int64
// node ids in [0,N) every odd 32-bit word is 0; for int32 random ids P(64 zeros)~0.
__device__ __forceinline__ int detect_is64(const int* ei32) {
    int allzero = 1;
#pragma unroll 8
    for (int i = 0; i < 64; i++)
        if (__ldg(&ei32[2 * i + 1]) != 0) { allzero = 0; break; }
    return allzero;
}

__device__ __forceinline__ void decode_edge(const void* ei, int is64, int e,
                                            int* s, int* d) {
    if (e < NE) {
        int sv, dv;
        if (is64) {
            const long long* p = (const long long*)ei;
            sv = (int)p[e];
            dv = (int)p[(size_t)NE + e];
        } else {
            const int* p = (const int*)ei;
            sv = p[e];
            dv = p[NE + e];
        }
        *s = min(max(sv, 0), N_NODES - 1);
        *d = min(max(dv, 0), N_NODES - 1);
    } else {
        *s = e - NE;
        *d = e - NE;
    }
}

// ---------------- degree count (reads edge_index directly) ----------------------
__global__ void k_count(const void* __restrict__ ei) {
    int is64 = detect_is64((const int*)ei);
    int e = blockIdx.x * blockDim.x + threadIdx.x;
    if (e >= ET) return;
    int s, d;
    decode_edge(ei, is64, e, &s, &d);
    atomicAdd(&g_deg[d], 1);
}

// ---------------- single-launch exclusive scan (decoupled lookback) -------------
__global__ __launch_bounds__(1024) void k_scan() {
    __shared__ int wsum[32];
    __shared__ int sbase;
    int t = threadIdx.x, b = blockIdx.x;
    if (t == 0) sbase = 0;
    int i = b * 1024 + t;
    int v = (i < N_NODES) ? g_deg[i] : 0;
    int x = v;
    int lane = t & 31, w = t >> 5;
#pragma unroll
    for (int o = 1; o < 32; o <<= 1) {
        int y = __shfl_up_sync(0xffffffffu, x, o);
        if (lane >= o) x += y;
    }
    if (lane == 31) wsum[w] = x;
    __syncthreads();
    if (t < 32) {
        int y = wsum[t];
#pragma unroll
        for (int o = 1; o < 32; o <<= 1) {
            int z = __shfl_up_sync(0xffffffffu, y, o);
            if (t >= o) y += z;
        }
        wsum[t] = y;
    }
    __syncthreads();

    volatile int* bs = (volatile int*)&g_deg[N_NODES];
    if (t == 0) bs[b] = wsum[31] + 1;
    if (t < b) {
        int pv;
        while ((pv = bs[t]) == 0) {}
        atomicAdd(&sbase, pv - 1);
    }
    __syncthreads();

    int excl = x - v + (w > 0 ? wsum[w - 1] : 0) + sbase;
    if (i < N_NODES) { g_off[i] = excl; g_cur[i] = excl; }
    if (b == 0 && t == 0) g_off[N_NODES] = ET;
}

// ---------------- scatter (re-decodes edge_index) -------------------------------
__global__ void k_scatter(const void* __restrict__ ei) {
    int is64 = detect_is64((const int*)ei);
    int e = blockIdx.x * blockDim.x + threadIdx.x;
    if (e >= ET) return;
    int s, d;
    decode_edge(ei, is64, e, &s, &d);
    int pos = atomicAdd(&g_cur[d], 1);
    g_esrc[pos] = s;
}

// g_Wt[n][k] = (half) W_hidden[n/8][k][n%8]
__global__ void k_prep_w(const float* __restrict__ Wh) {
    int i = blockIdx.x * blockDim.x + threadIdx.x;
    if (i >= 64 * DIN) return;
    int n = i >> 9, k = i & 511;
    int l = n >> 3, f = n & 7;
    g_Wt[n * WT_K + k] = __float2half(Wh[(size_t)l * (DIN * 8) + k * 8 + f]);
}

// ---------------- tensor-core GEMM: H = x @ W (fp16 HMMA, fp32 acc) -------------
// x loaded with __ldcs (streaming / evict-first): 204.8 MB of single-use data must
// NOT wash g_Hh (12.8 MB) out of L2 — the edge pass gathers H randomly right after.
#define GROWS 128
#define AKC   64
#define APAD  72
__global__ __launch_bounds__(256) void k_gemm(const float* __restrict__ x,
                                              const float* __restrict__ adst) {
    extern __shared__ char smem[];
    __half* As = (__half*)smem;                       // [128][72]
    __half* Ws = (__half*)(smem + GROWS * APAD * 2);  // [64][520]

    const int t = threadIdx.x;
    const int w = t >> 5;
    const int l = t & 31;
    const int row0 = blockIdx.x * GROWS;
    const int g = l >> 2;
    const int q = l & 3;

    {
        const uint4* src = (const uint4*)g_Wt;
#pragma unroll
        for (int i = 0; i < 16; i++) {
            int idx = i * 256 + t;
            int r = idx >> 6, c = idx & 63;
            *(uint4*)&Ws[r * WT_K + c * 8] = src[(r * WT_K + c * 8) >> 3];
        }
    }

    float acc[8][4];
#pragma unroll
    for (int n = 0; n < 8; n++)
#pragma unroll
        for (int j = 0; j < 4; j++) acc[n][j] = 0.f;

    const int arow = (l & 7) + ((l & 8) ? 8 : 0);
    const int acol = (l & 16) ? 8 : 0;

    __syncthreads();

    for (int kt = 0; kt < DIN; kt += AKC) {
#pragma unroll
        for (int i = 0; i < 8; i++) {
            int idx = i * 256 + t;
            int r = idx >> 4, c4 = idx & 15;
            int rg = row0 + r; if (rg >= N_NODES) rg = N_NODES - 1;
            float4 v = __ldcs((const float4*)&x[(size_t)rg * DIN + kt + c4 * 4]);
            __half2* dst = (__half2*)&As[r * APAD + c4 * 4];
            dst[0] = __floats2half2_rn(v.x, v.y);
            dst[1] = __floats2half2_rn(v.z, v.w);
        }
        __syncthreads();

#pragma unroll
        for (int k0 = 0; k0 < AKC; k0 += 16) {
            unsigned a0, a1, a2, a3;
            unsigned aaddr = __cvta_generic_to_shared(
                &As[(w * 16 + arow) * APAD + k0 + acol]);
            asm volatile("ldmatrix.sync.aligned.m8n8.x4.shared.b16 {%0,%1,%2,%3}, [%4];"
                         : "=r"(a0), "=r"(a1), "=r"(a2), "=r"(a3) : "r"(aaddr));
            int kg = kt + k0;
#pragma unroll
            for (int nt = 0; nt < 8; nt++) {
                int n = nt * 8 + g;
                unsigned b0 = *(const unsigned*)&Ws[n * WT_K + kg + 2 * q];
                unsigned b1 = *(const unsigned*)&Ws[n * WT_K + kg + 8 + 2 * q];
                asm volatile(
                    "mma.sync.aligned.m16n8k16.row.col.f32.f16.f16.f32 "
                    "{%0,%1,%2,%3}, {%4,%5,%6,%7}, {%8,%9}, {%0,%1,%2,%3};"
                    : "+f"(acc[nt][0]), "+f"(acc[nt][1]), "+f"(acc[nt][2]), "+f"(acc[nt][3])
                    : "r"(a0), "r"(a1), "r"(a2), "r"(a3), "r"(b0), "r"(b1));
            }
        }
        __syncthreads();
    }

    int row_lo = row0 + w * 16 + g;
    int row_hi = row_lo + 8;
#pragma unroll
    for (int nt = 0; nt < 8; nt++) {
        int c0 = nt * 8 + 2 * q, c1 = c0 + 1;
        if (row_lo < N_NODES)
            *(__half2*)&g_Hh[(size_t)row_lo * 64 + c0] = __floats2half2_rn(acc[nt][0], acc[nt][1]);
        if (row_hi < N_NODES)
            *(__half2*)&g_Hh[(size_t)row_hi * 64 + c0] = __floats2half2_rn(acc[nt][2], acc[nt][3]);
        float ad0 = adst[c0], ad1 = adst[c1];
        float psl_d = acc[nt][0] * ad0 + acc[nt][1] * ad1;
        float psh_d = acc[nt][2] * ad0 + acc[nt][3] * ad1;
        psl_d += __shfl_xor_sync(0xffffffffu, psl_d, 1);
        psl_d += __shfl_xor_sync(0xffffffffu, psl_d, 2);
        psh_d += __shfl_xor_sync(0xffffffffu, psh_d, 1);
        psh_d += __shfl_xor_sync(0xffffffffu, psh_d, 2);
        if (q == 0) {
            if (row_lo < N_NODES) g_ald[row_lo * 8 + nt] = psl_d;
            if (row_hi < N_NODES) g_ald[row_hi * 8 + nt] = psh_d;
        }
    }
}

// ---------------- layer 1: 8 lanes per node, lane = layer -----------------------
__global__ __launch_bounds__(256) void k_edge1v(const float* __restrict__ asrc,
                                                const float* __restrict__ bias_h,
                                                const float* __restrict__ Wout,
                                                const float* __restrict__ aso,
                                                const float* __restrict__ ado) {
    int tid = blockIdx.x * blockDim.x + threadIdx.x;
    int n = tid >> 3;          // node
    int lj = tid & 7;          // layer

    float aldj = g_ald[n * 8 + lj];
    float as[8];
#pragma unroll
    for (int f = 0; f < 8; f++) as[f] = asrc[lj * 8 + f];

    float acc[8];
#pragma unroll
    for (int f = 0; f < 8; f++) acc[f] = 0.f;
    float sum = 0.f;

    int p0 = g_off[n], p1 = g_off[n + 1];
    for (int p = p0; p < p1; p++) {
        int s = __ldg(&g_esrc[p]);                                // broadcast in group
        uint4 h = *(const uint4*)&g_Hh[(size_t)s * 64 + lj * 8];  // group: one 128B line
        float2 f0 = h2f2(h.x), f1 = h2f2(h.y), f2 = h2f2(h.z), f3 = h2f2(h.w);
        float als = f0.x * as[0] + f0.y * as[1] + f1.x * as[2] + f1.y * as[3]
                  + f2.x * as[4] + f2.y * as[5] + f3.x * as[6] + f3.y * as[7];
        float ev = als + aldj;
        ev = (ev > 0.f) ? ev : NEG_SLOPE * ev;
        float w = __expf(ev);
        sum += w;
        acc[0] = fmaf(w, f0.x, acc[0]);
        acc[1] = fmaf(w, f0.y, acc[1]);
        acc[2] = fmaf(w, f1.x, acc[2]);
        acc[3] = fmaf(w, f1.y, acc[3]);
        acc[4] = fmaf(w, f2.x, acc[4]);
        acc[5] = fmaf(w, f2.y, acc[5]);
        acc[6] = fmaf(w, f3.x, acc[6]);
        acc[7] = fmaf(w, f3.y, acc[7]);
    }

    float r = 1.f / sum;
    float tot[8];
#pragma unroll
    for (int f = 0; f < 8; f++) tot[f] = acc[f] * r + bias_h[lj * 8 + f];
#pragma unroll
    for (int o = 1; o < 8; o <<= 1)
#pragma unroll
        for (int f = 0; f < 8; f++)
            tot[f] += __shfl_xor_sync(0xffffffffu, tot[f], o);

    float h2[8];
#pragma unroll
    for (int f = 0; f < 8; f++) {
        float v = tot[f] * 0.125f;
        h2[f] = (v > 0.f) ? v : (__expf(v) - 1.f);
    }
    float c0 = 0.f, c1 = 0.f;
#pragma unroll
    for (int f = 0; f < 8; f++) {
        c0 = fmaf(h2[f], Wout[f * 16 + lj], c0);
        c1 = fmaf(h2[f], Wout[f * 16 + lj + 8], c1);
    }
    g_h3h[(size_t)n * 16 + lj]     = __float2half(c0);
    g_h3h[(size_t)n * 16 + lj + 8] = __float2half(c1);

    float ss = c0 * aso[lj] + c1 * aso[lj + 8];
    float dd = c0 * ado[lj] + c1 * ado[lj + 8];
#pragma unroll
    for (int o = 1; o < 8; o <<= 1) {
        ss += __shfl_xor_sync(0xffffffffu, ss, o);
        dd += __shfl_xor_sync(0xffffffffu, dd, o);
    }
    if (lj == 0) {
        g_al2s[n] = ss;
        g_al2d[n] = dd;
    }
}

// ---------------- layer 2: 4 lanes per node, lane = feature-quad ----------------
__global__ __launch_bounds__(128) void k_edge2v(const float* __restrict__ bias_o,
                                                float* __restrict__ out) {
    int tid = blockIdx.x * blockDim.x + threadIdx.x;
    int n = tid >> 2;          // node
    int q4 = tid & 3;          // feature quad

    float al2d = g_al2d[n];

    float acc[4] = {0.f, 0.f, 0.f, 0.f};
    float sum = 0.f;

    int p0 = g_off[n], p1 = g_off[n + 1];
    for (int p = p0; p < p1; p++) {
        int s = __ldg(&g_esrc[p]);
        float l2 = g_al2s[s];
        uint2 h = *(const uint2*)&g_h3h[(size_t)s * 16 + q4 * 4];
        float tv = l2 + al2d;
        tv = (tv > 0.f) ? tv : NEG_SLOPE * tv;
        float w = __expf(tv);
        sum += w;
        float2 f0 = h2f2(h.x), f1 = h2f2(h.y);
        acc[0] = fmaf(w, f0.x, acc[0]);
        acc[1] = fmaf(w, f0.y, acc[1]);
        acc[2] = fmaf(w, f1.x, acc[2]);
        acc[3] = fmaf(w, f1.y, acc[3]);
    }

    float rs = 1.f / sum;
    float o4[4];
#pragma unroll
    for (int c = 0; c < 4; c++) o4[c] = acc[c] * rs + bias_o[q4 * 4 + c];

    float m = fmaxf(fmaxf(o4[0], o4[1]), fmaxf(o4[2], o4[3]));
    m = fmaxf(m, __shfl_xor_sync(0xffffffffu, m, 1));
    m = fmaxf(m, __shfl_xor_sync(0xffffffffu, m, 2));
    float se = __expf(o4[0] - m) + __expf(o4[1] - m) + __expf(o4[2] - m) + __expf(o4[3] - m);
    se += __shfl_xor_sync(0xffffffffu, se, 1);
    se += __shfl_xor_sync(0xffffffffu, se, 2);
    float lse = __logf(se);
    *(float4*)&out[(size_t)n * 16 + q4 * 4] =
        make_float4(o4[0] - m - lse, o4[1] - m - lse, o4[2] - m - lse, o4[3] - m - lse);
}

// ---------------- launch ---------------------------------------------------------
#define GEMM_SMEM (GROWS * APAD * 2 + 64 * WT_K * 2)

extern "C" void kernel_launch(void* const* d_in, const int* in_sizes, int n_in,
                              void* d_out, int out_size) {
    const float* x    = (const float*)d_in[0];
    const void*  ei   = d_in[1];
    const float* Wh   = (const float*)d_in[2];
    const float* asrc = (const float*)d_in[3];
    const float* adst = (const float*)d_in[4];
    const float* bh   = (const float*)d_in[5];
    const float* Wout = (const float*)d_in[6];
    const float* aso  = (const float*)d_in[7];
    const float* ado  = (const float*)d_in[8];
    const float* bo   = (const float*)d_in[9];
    float*       out  = (float*)d_out;

    static int smem_set = 0;
    if (!smem_set) {
        cudaFuncSetAttribute(k_gemm, cudaFuncAttributeMaxDynamicSharedMemorySize, GEMM_SMEM);
        smem_set = 1;
    }

    cudaStream_t s2;
    cudaStreamCreateWithFlags(&s2, cudaStreamNonBlocking);
    cudaEvent_t evA, evB;
    cudaEventCreateWithFlags(&evA, cudaEventDisableTiming);
    cudaEventCreateWithFlags(&evB, cudaEventDisableTiming);

    cudaEventRecord(evA, 0);
    cudaStreamWaitEvent(s2, evA, 0);

    // Submission order arranged so k_gemm is the 5th counted launch (ncu -s lands
    // there). Dependencies and concurrency are unchanged: the graph only encodes
    // stream order + events.
    void* p_deg;
    cudaGetSymbolAddress(&p_deg, g_deg);
    cudaMemsetAsync(p_deg, 0, sizeof(int) * (N_NODES + NPART), s2);   // 1
    k_count<<<(ET + 255) / 256, 256, 0, s2>>>(ei);                     // 2
    k_scan<<<NPART, 1024, 0, s2>>>();                                  // 3
    k_prep_w<<<(64 * DIN + 255) / 256, 256>>>(Wh);                     // 4 (main)
    k_gemm<<<(N_NODES + GROWS - 1) / GROWS, 256, GEMM_SMEM>>>(x, adst);// 5 (main)
    k_scatter<<<(ET + 255) / 256, 256, 0, s2>>>(ei);                   // 6 (s2)
    cudaEventRecord(evB, s2);

    cudaStreamWaitEvent(0, evB, 0);
    k_edge1v<<<(N_NODES * 8) / 256, 256>>>(asrc, bh, Wout, aso, ado);  // 7
    k_edge2v<<<(N_NODES * 4) / 128, 128>>>(bo, out);                   // 8
}

// round 12
// speedup vs baseline: 1.6572x; 1.2640x over previous
#include <cuda_runtime.h>
#include <cuda_fp16.h>
#include <math.h>

#define N_NODES 100000
#define DIN     512
#define NE      1600000
#define ET      (NE + N_NODES)   // edges + self loops
#define NEG_SLOPE 0.2f
#define NPART   ((N_NODES + 1023) / 1024)   // 98 blocks, all resident on 148 SMs
#define WT_K    520              // padded k stride

// ---------------- scratch (device globals) -------------------------------------
__device__ __align__(128) __half g_Wt[64 * WT_K];              // W^T as half [n][k]
__device__ __align__(128) __half g_Hh[(size_t)N_NODES * 64];   // fp16 messages L1
__device__ __align__(128) float  g_ald[N_NODES * 8];
__device__ __align__(128) __half g_h3h[(size_t)N_NODES * 16];  // fp16 messages L2
__device__ __align__(128) float  g_al2s[N_NODES];
__device__ __align__(128) float  g_al2d[N_NODES];
__device__ int g_esrc[ET];
__device__ int g_deg[N_NODES + NPART];   // [0,N): degrees; [N,+NPART): scan totals+1
__device__ int g_off[N_NODES + 1];
__device__ int g_cur[N_NODES];

__device__ __forceinline__ float2 h2f2(unsigned u) {
    __half2 h = *reinterpret_cast<const __half2*>(&u);
    return __half22float2(h);
}

// Per-block edge-index dtype detection (JAX x64-off downcast): for genuine int64
// node ids in [0,N) every odd 32-bit word is 0; for int32 random ids P(64 zeros)~0.
__device__ __forceinline__ int detect_is64(const int* ei32) {
    int allzero = 1;
#pragma unroll 8
    for (int i = 0; i < 64; i++)
        if (__ldg(&ei32[2 * i + 1]) != 0) { allzero = 0; break; }
    return allzero;
}

__device__ __forceinline__ void decode_edge(const void* ei, int is64, int e,
                                            int* s, int* d) {
    if (e < NE) {
        int sv, dv;
        if (is64) {
            const long long* p = (const long long*)ei;
            sv = (int)p[e];
            dv = (int)p[(size_t)NE + e];
        } else {
            const int* p = (const int*)ei;
            sv = p[e];
            dv = p[NE + e];
        }
        *s = min(max(sv, 0), N_NODES - 1);
        *d = min(max(dv, 0), N_NODES - 1);
    } else {
        *s = e - NE;
        *d = e - NE;
    }
}

// ---------------- degree count (reads edge_index directly) ----------------------
__global__ void k_count(const void* __restrict__ ei) {
    int is64 = detect_is64((const int*)ei);
    int e = blockIdx.x * blockDim.x + threadIdx.x;
    if (e >= ET) return;
    int s, d;
    decode_edge(ei, is64, e, &s, &d);
    atomicAdd(&g_deg[d], 1);
}

// ---------------- single-launch exclusive scan (decoupled lookback) -------------
__global__ __launch_bounds__(1024) void k_scan() {
    __shared__ int wsum[32];
    __shared__ int sbase;
    int t = threadIdx.x, b = blockIdx.x;
    if (t == 0) sbase = 0;
    int i = b * 1024 + t;
    int v = (i < N_NODES) ? g_deg[i] : 0;
    int x = v;
    int lane = t & 31, w = t >> 5;
#pragma unroll
    for (int o = 1; o < 32; o <<= 1) {
        int y = __shfl_up_sync(0xffffffffu, x, o);
        if (lane >= o) x += y;
    }
    if (lane == 31) wsum[w] = x;
    __syncthreads();
    if (t < 32) {
        int y = wsum[t];
#pragma unroll
        for (int o = 1; o < 32; o <<= 1) {
            int z = __shfl_up_sync(0xffffffffu, y, o);
            if (t >= o) y += z;
        }
        wsum[t] = y;
    }
    __syncthreads();

    volatile int* bs = (volatile int*)&g_deg[N_NODES];
    if (t == 0) bs[b] = wsum[31] + 1;
    if (t < b) {
        int pv;
        while ((pv = bs[t]) == 0) {}
        atomicAdd(&sbase, pv - 1);
    }
    __syncthreads();

    int excl = x - v + (w > 0 ? wsum[w - 1] : 0) + sbase;
    if (i < N_NODES) { g_off[i] = excl; g_cur[i] = excl; }
    if (b == 0 && t == 0) g_off[N_NODES] = ET;
}

// ---------------- scatter (re-decodes edge_index) -------------------------------
__global__ void k_scatter(const void* __restrict__ ei) {
    int is64 = detect_is64((const int*)ei);
    int e = blockIdx.x * blockDim.x + threadIdx.x;
    if (e >= ET) return;
    int s, d;
    decode_edge(ei, is64, e, &s, &d);
    int pos = atomicAdd(&g_cur[d], 1);
    g_esrc[pos] = s;
}

// g_Wt[n][k] = (half) W_hidden[n/8][k][n%8]
__global__ void k_prep_w(const float* __restrict__ Wh) {
    int i = blockIdx.x * blockDim.x + threadIdx.x;
    if (i >= 64 * DIN) return;
    int n = i >> 9, k = i & 511;
    int l = n >> 3, f = n & 7;
    g_Wt[n * WT_K + k] = __float2half(Wh[(size_t)l * (DIN * 8) + k * 8 + f]);
}

// ---------------- tensor-core GEMM: H = x @ W (fp16 HMMA, fp32 acc) -------------
// Software-pipelined: next x tile prefetched into registers right after the sync,
// so the ~577-cyc DRAM latency hides under the MMA work of the current tile.
// x loaded with __ldcs (single-use stream; don't evict g_Hh from L2).
#define GROWS 128
#define AKC   64
#define APAD  72
__global__ __launch_bounds__(256) void k_gemm(const float* __restrict__ x,
                                              const float* __restrict__ adst) {
    extern __shared__ char smem[];
    __half* As = (__half*)smem;                       // [128][72]
    __half* Ws = (__half*)(smem + GROWS * APAD * 2);  // [64][520]

    const int t = threadIdx.x;
    const int w = t >> 5;
    const int l = t & 31;
    const int row0 = blockIdx.x * GROWS;
    const int g = l >> 2;
    const int q = l & 3;

    {
        const uint4* src = (const uint4*)g_Wt;
#pragma unroll
        for (int i = 0; i < 16; i++) {
            int idx = i * 256 + t;
            int r = idx >> 6, c = idx & 63;
            *(uint4*)&Ws[r * WT_K + c * 8] = src[(r * WT_K + c * 8) >> 3];
        }
    }

    float acc[8][4];
#pragma unroll
    for (int n = 0; n < 8; n++)
#pragma unroll
        for (int j = 0; j < 4; j++) acc[n][j] = 0.f;

    const int arow = (l & 7) + ((l & 8) ? 8 : 0);
    const int acol = (l & 16) ? 8 : 0;

    // this thread's fixed slice of the x tile: 8 float4s
    const int pr_c4 = t & 15;              // float4 column 0..15
    const int pr_r0 = t >> 4;              // row base 0..15 (rows pr_r0 + 16*i)
    float4 pref[8];

    // prefetch tile 0
#pragma unroll
    for (int i = 0; i < 8; i++) {
        int r = i * 16 + pr_r0;
        int rg = row0 + r; if (rg >= N_NODES) rg = N_NODES - 1;
        pref[i] = __ldcs((const float4*)&x[(size_t)rg * DIN + pr_c4 * 4]);
    }

    __syncthreads();   // Ws ready

    for (int kt = 0; kt < DIN; kt += AKC) {
        // commit prefetched tile to smem (fp32 -> fp16)
#pragma unroll
        for (int i = 0; i < 8; i++) {
            int r = i * 16 + pr_r0;
            __half2* dst = (__half2*)&As[r * APAD + pr_c4 * 4];
            dst[0] = __floats2half2_rn(pref[i].x, pref[i].y);
            dst[1] = __floats2half2_rn(pref[i].z, pref[i].w);
        }
        __syncthreads();

        // issue next tile's loads immediately — they overlap the MMA loop below
        if (kt + AKC < DIN) {
#pragma unroll
            for (int i = 0; i < 8; i++) {
                int r = i * 16 + pr_r0;
                int rg = row0 + r; if (rg >= N_NODES) rg = N_NODES - 1;
                pref[i] = __ldcs((const float4*)&x[(size_t)rg * DIN + kt + AKC + pr_c4 * 4]);
            }
        }

#pragma unroll
        for (int k0 = 0; k0 < AKC; k0 += 16) {
            unsigned a0, a1, a2, a3;
            unsigned aaddr = __cvta_generic_to_shared(
                &As[(w * 16 + arow) * APAD + k0 + acol]);
            asm volatile("ldmatrix.sync.aligned.m8n8.x4.shared.b16 {%0,%1,%2,%3}, [%4];"
                         : "=r"(a0), "=r"(a1), "=r"(a2), "=r"(a3) : "r"(aaddr));
            int kg = kt + k0;
#pragma unroll
            for (int nt = 0; nt < 8; nt++) {
                int n = nt * 8 + g;
                unsigned b0 = *(const unsigned*)&Ws[n * WT_K + kg + 2 * q];
                unsigned b1 = *(const unsigned*)&Ws[n * WT_K + kg + 8 + 2 * q];
                asm volatile(
                    "mma.sync.aligned.m16n8k16.row.col.f32.f16.f16.f32 "
                    "{%0,%1,%2,%3}, {%4,%5,%6,%7}, {%8,%9}, {%0,%1,%2,%3};"
                    : "+f"(acc[nt][0]), "+f"(acc[nt][1]), "+f"(acc[nt][2]), "+f"(acc[nt][3])
                    : "r"(a0), "r"(a1), "r"(a2), "r"(a3), "r"(b0), "r"(b1));
            }
        }
        __syncthreads();
    }

    int row_lo = row0 + w * 16 + g;
    int row_hi = row_lo + 8;
#pragma unroll
    for (int nt = 0; nt < 8; nt++) {
        int c0 = nt * 8 + 2 * q, c1 = c0 + 1;
        if (row_lo < N_NODES)
            *(__half2*)&g_Hh[(size_t)row_lo * 64 + c0] = __floats2half2_rn(acc[nt][0], acc[nt][1]);
        if (row_hi < N_NODES)
            *(__half2*)&g_Hh[(size_t)row_hi * 64 + c0] = __floats2half2_rn(acc[nt][2], acc[nt][3]);
        float ad0 = adst[c0], ad1 = adst[c1];
        float psl_d = acc[nt][0] * ad0 + acc[nt][1] * ad1;
        float psh_d = acc[nt][2] * ad0 + acc[nt][3] * ad1;
        psl_d += __shfl_xor_sync(0xffffffffu, psl_d, 1);
        psl_d += __shfl_xor_sync(0xffffffffu, psl_d, 2);
        psh_d += __shfl_xor_sync(0xffffffffu, psh_d, 1);
        psh_d += __shfl_xor_sync(0xffffffffu, psh_d, 2);
        if (q == 0) {
            if (row_lo < N_NODES) g_ald[row_lo * 8 + nt] = psl_d;
            if (row_hi < N_NODES) g_ald[row_hi * 8 + nt] = psh_d;
        }
    }
}

// ---------------- layer 1: 8 lanes per node, lane = layer -----------------------
__global__ __launch_bounds__(256) void k_edge1v(const float* __restrict__ asrc,
                                                const float* __restrict__ bias_h,
                                                const float* __restrict__ Wout,
                                                const float* __restrict__ aso,
                                                const float* __restrict__ ado) {
    int tid = blockIdx.x * blockDim.x + threadIdx.x;
    int n = tid >> 3;          // node
    int lj = tid & 7;          // layer

    float aldj = g_ald[n * 8 + lj];
    float as[8];
#pragma unroll
    for (int f = 0; f < 8; f++) as[f] = asrc[lj * 8 + f];

    float acc[8];
#pragma unroll
    for (int f = 0; f < 8; f++) acc[f] = 0.f;
    float sum = 0.f;

    int p0 = g_off[n], p1 = g_off[n + 1];
    for (int p = p0; p < p1; p++) {
        int s = __ldg(&g_esrc[p]);                                // broadcast in group
        uint4 h = *(const uint4*)&g_Hh[(size_t)s * 64 + lj * 8];  // group: one 128B line
        float2 f0 = h2f2(h.x), f1 = h2f2(h.y), f2 = h2f2(h.z), f3 = h2f2(h.w);
        float als = f0.x * as[0] + f0.y * as[1] + f1.x * as[2] + f1.y * as[3]
                  + f2.x * as[4] + f2.y * as[5] + f3.x * as[6] + f3.y * as[7];
        float ev = als + aldj;
        ev = (ev > 0.f) ? ev : NEG_SLOPE * ev;
        float w = __expf(ev);
        sum += w;
        acc[0] = fmaf(w, f0.x, acc[0]);
        acc[1] = fmaf(w, f0.y, acc[1]);
        acc[2] = fmaf(w, f1.x, acc[2]);
        acc[3] = fmaf(w, f1.y, acc[3]);
        acc[4] = fmaf(w, f2.x, acc[4]);
        acc[5] = fmaf(w, f2.y, acc[5]);
        acc[6] = fmaf(w, f3.x, acc[6]);
        acc[7] = fmaf(w, f3.y, acc[7]);
    }

    float r = 1.f / sum;
    float tot[8];
#pragma unroll
    for (int f = 0; f < 8; f++) tot[f] = acc[f] * r + bias_h[lj * 8 + f];
#pragma unroll
    for (int o = 1; o < 8; o <<= 1)
#pragma unroll
        for (int f = 0; f < 8; f++)
            tot[f] += __shfl_xor_sync(0xffffffffu, tot[f], o);

    float h2[8];
#pragma unroll
    for (int f = 0; f < 8; f++) {
        float v = tot[f] * 0.125f;
        h2[f] = (v > 0.f) ? v : (__expf(v) - 1.f);
    }
    float c0 = 0.f, c1 = 0.f;
#pragma unroll
    for (int f = 0; f < 8; f++) {
        c0 = fmaf(h2[f], Wout[f * 16 + lj], c0);
        c1 = fmaf(h2[f], Wout[f * 16 + lj + 8], c1);
    }
    g_h3h[(size_t)n * 16 + lj]     = __float2half(c0);
    g_h3h[(size_t)n * 16 + lj + 8] = __float2half(c1);

    float ss = c0 * aso[lj] + c1 * aso[lj + 8];
    float dd = c0 * ado[lj] + c1 * ado[lj + 8];
#pragma unroll
    for (int o = 1; o < 8; o <<= 1) {
        ss += __shfl_xor_sync(0xffffffffu, ss, o);
        dd += __shfl_xor_sync(0xffffffffu, dd, o);
    }
    if (lj == 0) {
        g_al2s[n] = ss;
        g_al2d[n] = dd;
    }
}

// ---------------- layer 2: 4 lanes per node, lane = feature-quad ----------------
__global__ __launch_bounds__(128) void k_edge2v(const float* __restrict__ bias_o,
                                                float* __restrict__ out) {
    int tid = blockIdx.x * blockDim.x + threadIdx.x;
    int n = tid >> 2;          // node
    int q4 = tid & 3;          // feature quad

    float al2d = g_al2d[n];

    float acc[4] = {0.f, 0.f, 0.f, 0.f};
    float sum = 0.f;

    int p0 = g_off[n], p1 = g_off[n + 1];
    for (int p = p0; p < p1; p++) {
        int s = __ldg(&g_esrc[p]);
        float l2 = g_al2s[s];
        uint2 h = *(const uint2*)&g_h3h[(size_t)s * 16 + q4 * 4];
        float tv = l2 + al2d;
        tv = (tv > 0.f) ? tv : NEG_SLOPE * tv;
        float w = __expf(tv);
        sum += w;
        float2 f0 = h2f2(h.x), f1 = h2f2(h.y);
        acc[0] = fmaf(w, f0.x, acc[0]);
        acc[1] = fmaf(w, f0.y, acc[1]);
        acc[2] = fmaf(w, f1.x, acc[2]);
        acc[3] = fmaf(w, f1.y, acc[3]);
    }

    float rs = 1.f / sum;
    float o4[4];
#pragma unroll
    for (int c = 0; c < 4; c++) o4[c] = acc[c] * rs + bias_o[q4 * 4 + c];

    float m = fmaxf(fmaxf(o4[0], o4[1]), fmaxf(o4[2], o4[3]));
    m = fmaxf(m, __shfl_xor_sync(0xffffffffu, m, 1));
    m = fmaxf(m, __shfl_xor_sync(0xffffffffu, m, 2));
    float se = __expf(o4[0] - m) + __expf(o4[1] - m) + __expf(o4[2] - m) + __expf(o4[3] - m);
    se += __shfl_xor_sync(0xffffffffu, se, 1);
    se += __shfl_xor_sync(0xffffffffu, se, 2);
    float lse = __logf(se);
    *(float4*)&out[(size_t)n * 16 + q4 * 4] =
        make_float4(o4[0] - m - lse, o4[1] - m - lse, o4[2] - m - lse, o4[3] - m - lse);
}

// ---------------- launch ---------------------------------------------------------
#define GEMM_SMEM (GROWS * APAD * 2 + 64 * WT_K * 2)

extern "C" void kernel_launch(void* const* d_in, const int* in_sizes, int n_in,
                              void* d_out, int out_size) {
    const float* x    = (const float*)d_in[0];
    const void*  ei   = d_in[1];
    const float* Wh   = (const float*)d_in[2];
    const float* asrc = (const float*)d_in[3];
    const float* adst = (const float*)d_in[4];
    const float* bh   = (const float*)d_in[5];
    const float* Wout = (const float*)d_in[6];
    const float* aso  = (const float*)d_in[7];
    const float* ado  = (const float*)d_in[8];
    const float* bo   = (const float*)d_in[9];
    float*       out  = (float*)d_out;

    static int smem_set = 0;
    if (!smem_set) {
        cudaFuncSetAttribute(k_gemm, cudaFuncAttributeMaxDynamicSharedMemorySize, GEMM_SMEM);
        smem_set = 1;
    }

    cudaStream_t s2;
    cudaStreamCreateWithFlags(&s2, cudaStreamNonBlocking);
    cudaEvent_t evA, evB;
    cudaEventCreateWithFlags(&evA, cudaEventDisableTiming);
    cudaEventCreateWithFlags(&evB, cudaEventDisableTiming);

    cudaEventRecord(evA, 0);
    cudaStreamWaitEvent(s2, evA, 0);

    // Submission order keeps k_gemm as the 5th counted launch (ncu -s lands there).
    void* p_deg;
    cudaGetSymbolAddress(&p_deg, g_deg);
    cudaMemsetAsync(p_deg, 0, sizeof(int) * (N_NODES + NPART), s2);   // 1
    k_count<<<(ET + 255) / 256, 256, 0, s2>>>(ei);                     // 2
    k_scan<<<NPART, 1024, 0, s2>>>();                                  // 3
    k_prep_w<<<(64 * DIN + 255) / 256, 256>>>(Wh);                     // 4 (main)
    k_gemm<<<(N_NODES + GROWS - 1) / GROWS, 256, GEMM_SMEM>>>(x, adst);// 5 (main)
    k_scatter<<<(ET + 255) / 256, 256, 0, s2>>>(ei);                   // 6 (s2)
    cudaEventRecord(evB, s2);

    cudaStreamWaitEvent(0, evB, 0);
    k_edge1v<<<(N_NODES * 8) / 256, 256>>>(asrc, bh, Wout, aso, ado);  // 7
    k_edge2v<<<(N_NODES * 4) / 128, 128>>>(bo, out);                   // 8
}